// round 15
// baseline (speedup 1.0000x reference)
#include <cuda_runtime.h>
#include <math.h>

#define B 128

__device__ float g_h1[B * 1024];
__device__ float g_h2[B * 512];
__device__ float g_aw2[256 * 512];   // pre-clamped W2 (written by L0 prologue)
__device__ float g_aw3[128 * 256];   // pre-clamped W3 (written by L0 prologue)

__device__ __forceinline__ float ex2f(float x) {
    float y;
    asm("ex2.approx.f32 %0, %1;" : "=f"(y) : "f"(x));
    return y;
}

// identity on [0,1], slope 0.1 outside
__device__ __forceinline__ float leaky_clamp01(float w) {
    float r = w;
    if (w < 0.0f)      r = 0.1f * w;
    else if (w > 1.0f) r = 1.0f + 0.1f * (w - 1.0f);
    return r;
}

__device__ __forceinline__ float tau_scale(const float* taup, float tau_floor) {
    float ta  = __ldg(taup);
    float tau = tau_floor + (ta >= 0.0f ? ta : 0.05f * ta);  // leaky_relu
    return tau * 1.4426950408889634f;                        // tau * log2(e)
}

// ============================================================================
// Chunked kernel (big layers), R12-proven shapes. Thread owns ONE (b,o).
// PRE: when PRE=true (L0), the block prologue also pre-clamps W2/W3 into
// g_aw2/g_aw3 (rides the idle fma/alu pipes of this MUFU-saturated kernel).
// ============================================================================
template <int IN, int BT, int OT, int KC, bool CAT, bool PRE>
__global__ __launch_bounds__(BT * OT) void layer_chunked(
    const float* __restrict__ h, const float* __restrict__ W,
    const float* __restrict__ taup, float tau_floor,
    float* __restrict__ out, int out_dim,
    const float* __restrict__ W2, const float* __restrict__ W3) {
    constexpr int T   = BT * OT;
    constexpr int KCP = KC + 4;
    __shared__ float ch[BT * KCP];
    __shared__ float aw[OT * KCP];

    const int tid   = threadIdx.x;
    const int obase = blockIdx.x * OT;
    const int bbase = blockIdx.y * BT;
    const int b     = tid % BT;
    const int o     = tid / BT;

    if (PRE) {
        // pre-clamp W2 (32768 float4) and W3 (8192 float4); 40960 total
        int gid = (blockIdx.y * gridDim.x + blockIdx.x) * T + tid;
        if (gid < 32768 + 8192) {
            const float4* src = (gid < 32768) ? (const float4*)W2 + gid
                                              : (const float4*)W3 + (gid - 32768);
            float4 v = *src;
            float4 r;
            r.x = leaky_clamp01(v.x); r.y = leaky_clamp01(v.y);
            r.z = leaky_clamp01(v.z); r.w = leaky_clamp01(v.w);
            if (gid < 32768) ((float4*)g_aw2)[gid] = r;
            else             ((float4*)g_aw3)[gid - 32768] = r;
        }
    }

    const float cs = tau_scale(taup, tau_floor);

    float num = 0.f, den = 0.f;

    for (int k0 = 0; k0 < IN; k0 += KC) {
        if (k0) __syncthreads();
        {   // stage activations (fused concat(x,1-x) for layer 0)
            const bool inv  = CAT && (k0 >= IN / 2);
            const float sc  = inv ? -cs : cs;
            const float off = inv ?  cs : 0.0f;
            const int hk0   = CAT ? (k0 & (IN / 2 - 1)) : k0;
            const int hstr  = CAT ? (IN / 2) : IN;
            #pragma unroll
            for (int i = tid; i < BT * (KC / 4); i += T) {
                int bb = i / (KC / 4), kv = i - bb * (KC / 4);
                float4 v = *(const float4*)&h[(bbase + bb) * hstr + hk0 + kv * 4];
                float4 r;
                r.x = fmaf(v.x, sc, off); r.y = fmaf(v.y, sc, off);
                r.z = fmaf(v.z, sc, off); r.w = fmaf(v.w, sc, off);
                *(float4*)&ch[bb * KCP + kv * 4] = r;
            }
        }
        #pragma unroll
        for (int i = tid; i < OT * (KC / 4); i += T) {
            int oo = i / (KC / 4), kv = i - oo * (KC / 4);
            float4 v = *(const float4*)&W[(obase + oo) * IN + k0 + kv * 4];
            float4 r;
            r.x = leaky_clamp01(v.x); r.y = leaky_clamp01(v.y);
            r.z = leaky_clamp01(v.z); r.w = leaky_clamp01(v.w);
            *(float4*)&aw[oo * KCP + kv * 4] = r;
        }
        __syncthreads();

        const float* cp = &ch[b * KCP];
        const float* ap = &aw[o * KCP];
        #pragma unroll 8
        for (int k = 0; k < KC; k += 4) {
            float4 c = *(const float4*)&cp[k];
            float4 a = *(const float4*)&ap[k];
            float z;
            z = c.x * a.x; { float e = ex2f(z); den += e; num = fmaf(e, z, num); }
            z = c.y * a.y; { float e = ex2f(z); den += e; num = fmaf(e, z, num); }
            z = c.z * a.z; { float e = ex2f(z); den += e; num = fmaf(e, z, num); }
            z = c.w * a.w; { float e = ex2f(z); den += e; num = fmaf(e, z, num); }
        }
    }

    out[(bbase + b) * out_dim + obase + o] = 1.0f - (num / den) / cs;
}

// ============================================================================
// Fused L2+L3 kernel. One block per batch row (rows are independent through
// the rest of the net). Phase A: h3 row (256 outs) from h2 row; Phase B:
// final out row (128 outs) from h3. Warp-per-output, lanes split K (coalesced
// LDG.128 of pre-clamped weights straight from L2; h rows live in smem).
// ============================================================================
__global__ __launch_bounds__(512) void fused_l2l3(
    const float* __restrict__ h2,
    const float* __restrict__ t2p, float tf2,
    const float* __restrict__ t3p, float tf3,
    float* __restrict__ out) {
    __shared__ float4 ch2[128];   // cs2 * h2 row (512 floats)
    __shared__ float  ch3[256];   // cs3 * h3 row

    const int tid = threadIdx.x;
    const int wid = tid >> 5;
    const int l   = tid & 31;
    const int b   = blockIdx.x;

    const float cs2 = tau_scale(t2p, tf2);
    const float cs3 = tau_scale(t3p, tf3);
    const float inv2 = 1.0f / cs2;
    const float inv3 = 1.0f / cs3;

    // stage cs2-scaled h2 row
    if (tid < 128) {
        float4 v = ((const float4*)(h2 + b * 512))[tid];
        float4 r;
        r.x = v.x * cs2; r.y = v.y * cs2; r.z = v.z * cs2; r.w = v.w * cs2;
        ch2[tid] = r;
    }
    __syncthreads();

    // Phase A: 256 outputs, 16 warps -> 16 outs/warp
    #pragma unroll
    for (int oi = 0; oi < 16; oi++) {
        const int o = wid + oi * 16;
        const float4* wp = (const float4*)(g_aw2 + o * 512);
        float num = 0.f, den = 0.f;
        #pragma unroll
        for (int p = 0; p < 4; p++) {
            float4 a = wp[p * 32 + l];
            float4 c = ch2[p * 32 + l];
            float z;
            z = c.x * a.x; { float e = ex2f(z); den += e; num = fmaf(e, z, num); }
            z = c.y * a.y; { float e = ex2f(z); den += e; num = fmaf(e, z, num); }
            z = c.z * a.z; { float e = ex2f(z); den += e; num = fmaf(e, z, num); }
            z = c.w * a.w; { float e = ex2f(z); den += e; num = fmaf(e, z, num); }
        }
        #pragma unroll
        for (int off = 16; off > 0; off >>= 1) {
            num += __shfl_xor_sync(0xFFFFFFFFu, num, off);
            den += __shfl_xor_sync(0xFFFFFFFFu, den, off);
        }
        if (l == 0)
            ch3[o] = cs3 * (1.0f - (num / den) * inv2);
    }
    __syncthreads();

    // Phase B: 128 outputs, 16 warps -> 8 outs/warp
    const float4* c3 = (const float4*)ch3;
    #pragma unroll
    for (int oi = 0; oi < 8; oi++) {
        const int o = wid + oi * 16;
        const float4* wp = (const float4*)(g_aw3 + o * 256);
        float num = 0.f, den = 0.f;
        #pragma unroll
        for (int p = 0; p < 2; p++) {
            float4 a = wp[p * 32 + l];
            float4 c = c3[p * 32 + l];
            float z;
            z = c.x * a.x; { float e = ex2f(z); den += e; num = fmaf(e, z, num); }
            z = c.y * a.y; { float e = ex2f(z); den += e; num = fmaf(e, z, num); }
            z = c.z * a.z; { float e = ex2f(z); den += e; num = fmaf(e, z, num); }
            z = c.w * a.w; { float e = ex2f(z); den += e; num = fmaf(e, z, num); }
        }
        #pragma unroll
        for (int off = 16; off > 0; off >>= 1) {
            num += __shfl_xor_sync(0xFFFFFFFFu, num, off);
            den += __shfl_xor_sync(0xFFFFFFFFu, den, off);
        }
        if (l == 0)
            out[b * 128 + o] = 1.0f - (num / den) * inv3;
    }
}

extern "C" void kernel_launch(void* const* d_in, const int* in_sizes, int n_in,
                              void* d_out, int out_size) {
    // metadata order: x, W0, tau0, W1, tau1, W2, tau2, W3, tau3
    const float* x  = (const float*)d_in[0];
    const float* W0 = (const float*)d_in[1];
    const float* t0 = (const float*)d_in[2];
    const float* W1 = (const float*)d_in[3];
    const float* t1 = (const float*)d_in[4];
    const float* W2 = (const float*)d_in[5];
    const float* t2 = (const float*)d_in[6];
    const float* W3 = (const float*)d_in[7];
    const float* t3 = (const float*)d_in[8];
    float* out = (float*)d_out;

    float *h1, *h2;
    cudaGetSymbolAddress((void**)&h1, g_h1);
    cudaGetSymbolAddress((void**)&h2, g_h2);

    // tau_floor = log(in-1) + log(0.95/0.05)
    const float L19 = 2.9444389791664403f;
    const float tf0 = logf(1023.0f) + L19;
    const float tf1 = logf(1023.0f) + L19;
    const float tf2 = logf(511.0f)  + L19;
    const float tf3 = logf(255.0f)  + L19;

    // L0: 1024->1024, fused concat + W2/W3 pre-clamp. 1024 blocks x 128 thr.
    layer_chunked<1024, 8, 16, 256, true, true>
        <<<dim3(1024 / 16, B / 8), 128>>>(x, W0, t0, tf0, h1, 1024, W2, W3);
    // L1: 1024->512. 512 blocks x 128 thr (R12-proven).
    layer_chunked<1024, 8, 16, 256, false, false>
        <<<dim3(512 / 16, B / 8), 128>>>(h1, W1, t1, tf1, h2, 512, nullptr, nullptr);
    // L2+L3 fused: one block per batch row. 128 blocks x 512 thr.
    fused_l2l3<<<B, 512>>>(h2, t2, tf2, t3, tf3, out);
}

// round 16
// speedup vs baseline: 1.1158x; 1.1158x over previous
#include <cuda_runtime.h>
#include <math.h>

#define B 128

__device__ float g_h1[B * 1024];
__device__ float g_h2[B * 512];
__device__ float g_h3[B * 256];
__device__ float g_aw1[512 * 1024];   // pre-clamped W1 (written in L0 prologue)
__device__ float g_aw2[256 * 512];    // pre-clamped W2
__device__ float g_aw3[128 * 256];    // pre-clamped W3

__device__ __forceinline__ float ex2f(float x) {
    float y;
    asm("ex2.approx.f32 %0, %1;" : "=f"(y) : "f"(x));
    return y;
}

// identity on [0,1], slope 0.1 outside
__device__ __forceinline__ float leaky_clamp01(float w) {
    float r = w;
    if (w < 0.0f)      r = 0.1f * w;
    else if (w > 1.0f) r = 1.0f + 0.1f * (w - 1.0f);
    return r;
}

__device__ __forceinline__ float tau_scale(const float* taup, float tau_floor) {
    float ta  = __ldg(taup);
    float tau = tau_floor + (ta >= 0.0f ? ta : 0.05f * ta);  // leaky_relu
    return tau * 1.4426950408889634f;                        // tau * log2(e)
}

// ============================================================================
// Chunked kernel (big layers), R12-proven shapes. Thread owns ONE (b,o).
// PRE (L0 only): prologue pre-clamps W1/W2/W3 into g_aw* on idle fma/alu pipes.
// CLAMPED: weights already clamped -> staging is a pure LDG->STS copy.
//   out[b,o] = 1 - (sum e^arg * arg)/(cs * sum e^arg), arg = cs*h[b,i]*aw[o,i]
// CAT: layer-0 mode, h is x[B][IN/2], staged as concat(x, 1-x).
// ============================================================================
template <int IN, int BT, int OT, int KC, bool CAT, bool PRE, bool CLAMPED>
__global__ __launch_bounds__(BT * OT) void layer_chunked(
    const float* __restrict__ h, const float* __restrict__ W,
    const float* __restrict__ taup, float tau_floor,
    float* __restrict__ out, int out_dim,
    const float* __restrict__ Wp1, const float* __restrict__ Wp2,
    const float* __restrict__ Wp3) {
    constexpr int T   = BT * OT;
    constexpr int KCP = KC + 4;
    __shared__ float ch[BT * KCP];
    __shared__ float aw[OT * KCP];

    const int tid   = threadIdx.x;
    const int obase = blockIdx.x * OT;
    const int bbase = blockIdx.y * BT;
    const int b     = tid % BT;
    const int o     = tid / BT;

    if (PRE) {
        // pre-clamp W1 (131072 f4) + W2 (32768 f4) + W3 (8192 f4) = 172032 f4
        const int NT  = gridDim.x * gridDim.y * T;
        int gid = (blockIdx.y * gridDim.x + blockIdx.x) * T + tid;
        for (int g = gid; g < 172032; g += NT) {
            const float4* src;
            float4* dst;
            if (g < 131072)      { src = (const float4*)Wp1 + g;            dst = (float4*)g_aw1 + g; }
            else if (g < 163840) { src = (const float4*)Wp2 + (g - 131072); dst = (float4*)g_aw2 + (g - 131072); }
            else                 { src = (const float4*)Wp3 + (g - 163840); dst = (float4*)g_aw3 + (g - 163840); }
            float4 v = *src, r;
            r.x = leaky_clamp01(v.x); r.y = leaky_clamp01(v.y);
            r.z = leaky_clamp01(v.z); r.w = leaky_clamp01(v.w);
            *dst = r;
        }
    }

    const float cs = tau_scale(taup, tau_floor);

    float num = 0.f, den = 0.f;

    for (int k0 = 0; k0 < IN; k0 += KC) {
        if (k0) __syncthreads();
        {   // stage activations (fused concat(x,1-x) for layer 0)
            const bool inv  = CAT && (k0 >= IN / 2);
            const float sc  = inv ? -cs : cs;
            const float off = inv ?  cs : 0.0f;
            const int hk0   = CAT ? (k0 & (IN / 2 - 1)) : k0;
            const int hstr  = CAT ? (IN / 2) : IN;
            #pragma unroll
            for (int i = tid; i < BT * (KC / 4); i += T) {
                int bb = i / (KC / 4), kv = i - bb * (KC / 4);
                float4 v = *(const float4*)&h[(bbase + bb) * hstr + hk0 + kv * 4];
                float4 r;
                r.x = fmaf(v.x, sc, off); r.y = fmaf(v.y, sc, off);
                r.z = fmaf(v.z, sc, off); r.w = fmaf(v.w, sc, off);
                *(float4*)&ch[bb * KCP + kv * 4] = r;
            }
        }
        #pragma unroll
        for (int i = tid; i < OT * (KC / 4); i += T) {
            int oo = i / (KC / 4), kv = i - oo * (KC / 4);
            float4 v = *(const float4*)&W[(obase + oo) * IN + k0 + kv * 4];
            if (!CLAMPED) {
                float4 r;
                r.x = leaky_clamp01(v.x); r.y = leaky_clamp01(v.y);
                r.z = leaky_clamp01(v.z); r.w = leaky_clamp01(v.w);
                *(float4*)&aw[oo * KCP + kv * 4] = r;
            } else {
                *(float4*)&aw[oo * KCP + kv * 4] = v;
            }
        }
        __syncthreads();

        const float* cp = &ch[b * KCP];
        const float* ap = &aw[o * KCP];
        #pragma unroll 8
        for (int k = 0; k < KC; k += 4) {
            float4 c = *(const float4*)&cp[k];
            float4 a = *(const float4*)&ap[k];
            float z;
            z = c.x * a.x; { float e = ex2f(z); den += e; num = fmaf(e, z, num); }
            z = c.y * a.y; { float e = ex2f(z); den += e; num = fmaf(e, z, num); }
            z = c.z * a.z; { float e = ex2f(z); den += e; num = fmaf(e, z, num); }
            z = c.w * a.w; { float e = ex2f(z); den += e; num = fmaf(e, z, num); }
        }
    }

    out[(bbase + b) * out_dim + obase + o] = 1.0f - (num / den) / cs;
}

// ============================================================================
// Split kernel (small layers, R12-proven shapes). Whole input staged once;
// S threads per output, each covering IN/S of K; partials reduced via smem.
// Weights come pre-clamped (pure copy staging).
// ============================================================================
template <int IN, int BT, int OT, int S>
__global__ __launch_bounds__(BT * OT * S) void layer_split(
    const float* __restrict__ h, const float* __restrict__ W,
    const float* __restrict__ taup, float tau_floor,
    float* __restrict__ out, int out_dim) {
    constexpr int T   = BT * OT * S;
    constexpr int G   = BT * OT;
    constexpr int KR  = IN / S;
    constexpr int INP = IN + 4;
    __shared__ float ch[BT * INP];
    __shared__ float aw[OT * INP];
    __shared__ float2 rpart[T];

    const int tid   = threadIdx.x;
    const int obase = blockIdx.x * OT;
    const int bbase = blockIdx.y * BT;
    const int idx   = tid & (G - 1);
    const int s     = tid / G;
    const int b     = idx % BT;
    const int o     = idx / BT;

    const float cs = tau_scale(taup, tau_floor);

    #pragma unroll
    for (int i = tid; i < BT * (IN / 4); i += T) {
        int bb = i / (IN / 4), kv = i - bb * (IN / 4);
        float4 v = *(const float4*)&h[(bbase + bb) * IN + kv * 4];
        float4 r; r.x = v.x * cs; r.y = v.y * cs; r.z = v.z * cs; r.w = v.w * cs;
        *(float4*)&ch[bb * INP + kv * 4] = r;
    }
    #pragma unroll
    for (int i = tid; i < OT * (IN / 4); i += T) {
        int oo = i / (IN / 4), kv = i - oo * (IN / 4);
        float4 v = *(const float4*)&W[(obase + oo) * IN + kv * 4];
        *(float4*)&aw[oo * INP + kv * 4] = v;   // pre-clamped
    }
    __syncthreads();

    float num = 0.0f, den = 0.0f;
    const float* cp = &ch[b * INP + s * KR];
    const float* ap = &aw[o * INP + s * KR];
    #pragma unroll 4
    for (int k = 0; k < KR; k += 4) {
        float4 c = *(const float4*)&cp[k];
        float4 a = *(const float4*)&ap[k];
        float z;
        z = c.x * a.x; { float e = ex2f(z); den += e; num = fmaf(e, z, num); }
        z = c.y * a.y; { float e = ex2f(z); den += e; num = fmaf(e, z, num); }
        z = c.z * a.z; { float e = ex2f(z); den += e; num = fmaf(e, z, num); }
        z = c.w * a.w; { float e = ex2f(z); den += e; num = fmaf(e, z, num); }
    }

    rpart[tid] = make_float2(num, den);
    __syncthreads();
    if (s == 0) {
        #pragma unroll
        for (int ss = 1; ss < S; ss++) {
            float2 p = rpart[idx + ss * G];
            num += p.x;
            den += p.y;
        }
        out[(bbase + b) * out_dim + obase + o] = 1.0f - (num / den) / cs;
    }
}

extern "C" void kernel_launch(void* const* d_in, const int* in_sizes, int n_in,
                              void* d_out, int out_size) {
    // metadata order: x, W0, tau0, W1, tau1, W2, tau2, W3, tau3
    const float* x  = (const float*)d_in[0];
    const float* W0 = (const float*)d_in[1];
    const float* t0 = (const float*)d_in[2];
    const float* W1 = (const float*)d_in[3];
    const float* t1 = (const float*)d_in[4];
    const float* W2 = (const float*)d_in[5];
    const float* t2 = (const float*)d_in[6];
    const float* W3 = (const float*)d_in[7];
    const float* t3 = (const float*)d_in[8];
    float* out = (float*)d_out;

    float *h1, *h2, *h3, *aw1, *aw2, *aw3;
    cudaGetSymbolAddress((void**)&h1, g_h1);
    cudaGetSymbolAddress((void**)&h2, g_h2);
    cudaGetSymbolAddress((void**)&h3, g_h3);
    cudaGetSymbolAddress((void**)&aw1, g_aw1);
    cudaGetSymbolAddress((void**)&aw2, g_aw2);
    cudaGetSymbolAddress((void**)&aw3, g_aw3);

    // tau_floor = log(in-1) + log(0.95/0.05)
    const float L19 = 2.9444389791664403f;
    const float tf0 = logf(1023.0f) + L19;
    const float tf1 = logf(1023.0f) + L19;
    const float tf2 = logf(511.0f)  + L19;
    const float tf3 = logf(255.0f)  + L19;

    // L0: 1024->1024, fused concat + pre-clamp of W1/W2/W3. 1024 blk x 128 thr.
    layer_chunked<1024, 8, 16, 256, true, true, false>
        <<<dim3(1024 / 16, B / 8), 128>>>(x, W0, t0, tf0, h1, 1024, W1, W2, W3);
    // L1: 1024->512, pre-clamped weights. 512 blocks x 128 thr.
    layer_chunked<1024, 8, 16, 256, false, false, true>
        <<<dim3(512 / 16, B / 8), 128>>>(h1, aw1, t1, tf1, h2, 512,
                                         nullptr, nullptr, nullptr);
    // L2: 512->256, 4-way split, pre-clamped. 512 blocks x 256 thr.
    layer_split<512, 8, 8, 4>
        <<<dim3(256 / 8, B / 8), 256>>>(h2, aw2, t2, tf2, h3, 256);
    // L3: 256->128, 4-way split, pre-clamped. 256 blocks x 256 thr.
    layer_split<256, 8, 8, 4>
        <<<dim3(128 / 8, B / 8), 256>>>(h3, aw3, t3, tf3, out, 128);
}